// round 9
// baseline (speedup 1.0000x reference)
#include <cuda_runtime.h>
#include <cuda_fp16.h>
#include <cstdint>

// Problem constants
#define MROWS  131072      // N*H*W*L
#define CDIM   256
#define NBATCH 512
#define HEADS  8
#define HD     32
#define LSEQ   256
// QK scale folded with log2(e): exp(s/sqrt(32)) = 2^(s * QEXP_SCALE)
#define QEXP_SCALE (0.17677669529663689f * 1.4426950408889634f)

// -------- scratch (device globals) --------
__device__ __half g_X[(size_t)MROWS * CDIM];
__device__ __half g_Q[(size_t)NBATCH * HEADS * LSEQ * HD];
__device__ __half g_K[(size_t)NBATCH * HEADS * LSEQ * HD];
__device__ __half g_V[(size_t)NBATCH * HEADS * LSEQ * HD];
__device__ __half g_O[(size_t)MROWS * CDIM];
__device__ __half g_Wt[4 * CDIM * CDIM];   // [w][n][k] = W_w[k][n] as half

// -------- helpers --------
__device__ __forceinline__ void mma16(float c[4], const unsigned a[4],
                                      unsigned b0, unsigned b1) {
    asm volatile(
        "mma.sync.aligned.m16n8k16.row.col.f32.f16.f16.f32 "
        "{%0,%1,%2,%3}, {%4,%5,%6,%7}, {%8,%9}, {%0,%1,%2,%3};"
        : "+f"(c[0]), "+f"(c[1]), "+f"(c[2]), "+f"(c[3])
        : "r"(a[0]), "r"(a[1]), "r"(a[2]), "r"(a[3]), "r"(b0), "r"(b1));
}
__device__ __forceinline__ unsigned pack2(float lo, float hi) {
    __half2 h = __floats2half2_rn(lo, hi);
    return *reinterpret_cast<unsigned*>(&h);
}
__device__ __forceinline__ unsigned ldu32(const __half* p) {
    return *reinterpret_cast<const unsigned*>(p);
}
__device__ __forceinline__ unsigned ex2h2(unsigned x) {
    unsigned r;
    asm("ex2.approx.f16x2 %0, %1;" : "=r"(r) : "r"(x));
    return r;
}
__device__ __forceinline__ uint32_t smem_u32(const void* p) {
    uint32_t a;
    asm("{ .reg .u64 t; cvta.to.shared.u64 t, %1; cvt.u32.u64 %0, t; }"
        : "=r"(a) : "l"(p));
    return a;
}
__device__ __forceinline__ void ldsm4(unsigned& r0, unsigned& r1,
                                      unsigned& r2, unsigned& r3, uint32_t a) {
    asm volatile("ldmatrix.sync.aligned.m8n8.x4.shared.b16 {%0,%1,%2,%3}, [%4];"
                 : "=r"(r0), "=r"(r1), "=r"(r2), "=r"(r3) : "r"(a));
}
__device__ __forceinline__ void cpasync16(uint32_t dst, const void* src) {
    asm volatile("cp.async.cg.shared.global [%0], [%1], 16;"
                 :: "r"(dst), "l"(src));
}

// ============================================================================
// pre-kernels: convert X to half; build Wt[w][n][k] = W_w[k][n] half
// ============================================================================
__global__ __launch_bounds__(256) void convert_x_kernel(
    const float* __restrict__ x, __half* __restrict__ xh)
{
    const size_t i = ((size_t)blockIdx.x * 256 + threadIdx.x) * 8;
    const float4 a = *(const float4*)(x + i);
    const float4 b = *(const float4*)(x + i + 4);
    uint4 v;
    v.x = pack2(a.x, a.y); v.y = pack2(a.z, a.w);
    v.z = pack2(b.x, b.y); v.w = pack2(b.z, b.w);
    *(uint4*)(xh + i) = v;
}

__global__ __launch_bounds__(256) void transpose_w_kernel(
    const float* __restrict__ W0, const float* __restrict__ W1,
    const float* __restrict__ W2, const float* __restrict__ W3,
    __half* __restrict__ Wt)
{
    __shared__ float tile[64][65];
    const int w  = blockIdx.z;
    const int k0 = blockIdx.x * 64;
    const int n0 = blockIdx.y * 64;
    const float* W = w == 0 ? W0 : (w == 1 ? W1 : (w == 2 ? W2 : W3));
    const int t = threadIdx.x;
    for (int i = t; i < 4096; i += 256) {
        const int r = i >> 6, c = i & 63;
        tile[c][r] = W[(k0 + r) * CDIM + n0 + c];
    }
    __syncthreads();
    for (int i = t; i < 4096; i += 256) {
        const int r = i >> 6, c = i & 63;
        Wt[(size_t)w * CDIM * CDIM + (n0 + r) * CDIM + k0 + c] = __float2half(tile[r][c]);
    }
}

// ============================================================================
// half GEMM (round-5 design, unchanged): cp.async double-buffered, ldmatrix,
// BM=128 BN=128 BK=64, 2 CTA/SM. MODE 0 Q-output pre-scaled by QEXP_SCALE.
// ============================================================================
#define GST 72
#define XS_HALFS (128 * GST)
#define GEMM_SMEM_BYTES (4 * XS_HALFS * 2)

template <int MODE>
__global__ __launch_bounds__(256, 2) void gemm2_kernel(
    const __half* __restrict__ X, const __half* __restrict__ Wt4,
    const float* __restrict__ b0p, const float* __restrict__ b1p,
    const float* __restrict__ b2p,
    void* __restrict__ o0, void* __restrict__ o1, void* __restrict__ o2)
{
    extern __shared__ __half smh[];
    const uint32_t sb = smem_u32(smh);

    const int t    = threadIdx.x;
    const int lane = t & 31;
    const int wid  = t >> 5;
    const int g    = lane >> 2;
    const int tg   = lane & 3;

    int widx = 0, nx = blockIdx.x;
    if (MODE == 0) { widx = nx >> 1; nx &= 1; }
    const int  n0 = nx * 128;
    const long m0 = (long)blockIdx.y * 128;
    const __half* Wt   = Wt4 + (size_t)widx * CDIM * CDIM;
    const float*  bias = widx == 0 ? b0p : (widx == 1 ? b1p : b2p);
    const float   osc  = (MODE == 0 && widx == 0) ? QEXP_SCALE : 1.0f;

    const int sr  = t >> 3;
    const int sc8 = (t & 7) * 8;

    auto issue = [&](int kb, int buf) {
        const __half* xs = X  + ((m0 + sr) << 8) + kb * 64 + sc8;
        const __half* ws = Wt + ((n0 + sr) << 8) + kb * 64 + sc8;
        const uint32_t xd = sb + (uint32_t)(buf * XS_HALFS + sr * GST + sc8) * 2;
        const uint32_t wd = sb + (uint32_t)((2 + buf) * XS_HALFS + sr * GST + sc8) * 2;
#pragma unroll
        for (int i = 0; i < 4; i++) {
            cpasync16(xd + i * 32 * GST * 2, xs + (i << 13));
            cpasync16(wd + i * 32 * GST * 2, ws + (i << 13));
        }
    };

    float acc[4][4][4] = {};

    const int m0w = (wid & 1) * 64;
    const int n0w = (wid >> 1) * 32;
    const int rr  = lane & 7;
    const int blk = lane >> 3;
    const int arow = m0w + (blk & 1) * 8 + rr;
    const int acol = (blk & 2) * 4;
    const int brow = n0w + ((blk & 2) ? 8 : 0) + rr;
    const int bcol = (blk & 1) * 8;

    issue(0, 0);
    asm volatile("cp.async.commit_group;");

#pragma unroll 1
    for (int kb = 0; kb < 4; kb++) {
        if (kb < 3) {
            issue(kb + 1, (kb + 1) & 1);
            asm volatile("cp.async.commit_group;");
            asm volatile("cp.async.wait_group 1;");
        } else {
            asm volatile("cp.async.wait_group 0;");
        }
        __syncthreads();

        const int buf = kb & 1;
        const uint32_t xbase = sb + (uint32_t)(buf * XS_HALFS) * 2;
        const uint32_t bbase = sb + (uint32_t)((2 + buf) * XS_HALFS) * 2;

#pragma unroll
        for (int kt = 0; kt < 4; kt++) {
            unsigned br[2][4];
#pragma unroll
            for (int nt2 = 0; nt2 < 2; nt2++)
                ldsm4(br[nt2][0], br[nt2][1], br[nt2][2], br[nt2][3],
                      bbase + (uint32_t)((brow + nt2 * 16) * GST + kt * 16 + bcol) * 2);
            unsigned ar[4][4];
#pragma unroll
            for (int mt = 0; mt < 4; mt++)
                ldsm4(ar[mt][0], ar[mt][1], ar[mt][2], ar[mt][3],
                      xbase + (uint32_t)((arow + mt * 16) * GST + kt * 16 + acol) * 2);
#pragma unroll
            for (int mt = 0; mt < 4; mt++) {
#pragma unroll
                for (int nt2 = 0; nt2 < 2; nt2++) {
                    mma16(acc[mt][nt2 * 2],     ar[mt], br[nt2][0], br[nt2][1]);
                    mma16(acc[mt][nt2 * 2 + 1], ar[mt], br[nt2][2], br[nt2][3]);
                }
            }
        }
        __syncthreads();
    }

#pragma unroll
    for (int mt = 0; mt < 4; mt++) {
#pragma unroll
        for (int hi = 0; hi < 2; hi++) {
            const long row = m0 + m0w + mt * 16 + hi * 8 + g;
#pragma unroll
            for (int nt = 0; nt < 4; nt++) {
                const int c = n0 + n0w + nt * 8 + 2 * tg;
                const float v0 = (acc[mt][nt][2 * hi]     + bias[c])     * osc;
                const float v1 = (acc[mt][nt][2 * hi + 1] + bias[c + 1]) * osc;
                if (MODE == 0) {
                    const long bb = row >> 8;
                    const int  l  = (int)(row & 255);
                    const int  ah = c >> 5;
                    const int  d  = c & 31;
                    __half* out = (__half*)(widx == 0 ? o0 : (widx == 1 ? o1 : o2));
                    *(unsigned*)(out + (((bb * HEADS + ah) * LSEQ + l) << 5) + d) = pack2(v0, v1);
                } else {
                    float2 v; v.x = v0; v.y = v1;
                    *(float2*)((float*)o0 + row * CDIM + c) = v;
                }
            }
        }
    }
}

// ============================================================================
// fp16 Attention v5: OCCUPANCY build.
//   16 q-rows per warp (one m16 tile) -> ~70 live regs -> 3 CTAs/SM
//   (6 warps/SMSP, occ 37.5%). CTA covers 128 rows; 2 CTAs per (batch,head).
//   Max-free softmax, exp2-scaled Q, ex2.f16x2, ones-row V row-sums,
//   ldmatrix fragments. No software pipelining.
// ============================================================================
__global__ __launch_bounds__(256, 3) void attn_f16_kernel(
    const __half* __restrict__ Q, const __half* __restrict__ K,
    const __half* __restrict__ V, __half* __restrict__ O)
{
    __shared__ __half Ks[LSEQ][40];    // [key][d]            20 KB
    __shared__ __half Vs[40][264];     // [d][key]+ones       21 KB

    const int t    = threadIdx.x;
    const int lane = t & 31;
    const int warp = t >> 5;
    const int g    = lane >> 2;
    const int tg   = lane & 3;

    const int  bh   = blockIdx.x >> 1;           // (batch,head)
    const int  half = blockIdx.x & 1;            // row half: 0 / 128
    const int  b    = bh >> 3;
    const int  ah   = bh & 7;
    const __half* Kg = K + (long)bh * LSEQ * HD;
    const __half* Vg = V + (long)bh * LSEQ * HD;
    const __half* Qw = Q + (long)bh * LSEQ * HD + (half * 128 + warp * 16) * HD;

    // ---- stage K ----
    for (int j = t; j < 2048; j += 256) {
        const int r = j >> 3, q = j & 7;
        *(uint2*)&Ks[r][q * 4] = *(const uint2*)(Kg + r * HD + q * 4);
    }
    // ---- stage V transposed ----
    for (int j = t; j < 4096; j += 256) {
        const int key = j >> 4, d2 = j & 15;
        const __half2 v = *(const __half2*)(Vg + key * HD + d2 * 2);
        Vs[2 * d2][key]     = __low2half(v);
        Vs[2 * d2 + 1][key] = __high2half(v);
    }
    // ---- ones row (d=32) and zero rows (33..39) ----
    const unsigned ONE2 = 0x3C003C00u;
    for (int j = t; j < 1056; j += 256) {
        const int r = j / 132, c = j % 132;
        *(unsigned*)&Vs[32 + r][c * 2] = (r == 0) ? ONE2 : 0u;
    }

    // ---- Q A-fragments (one m16 tile, 2 k16 steps) ----
    unsigned qa[2][4];
#pragma unroll
    for (int kt = 0; kt < 2; kt++) {
        const __half* qp = Qw + g * HD + kt * 16 + 2 * tg;
        qa[kt][0] = ldu32(qp);
        qa[kt][1] = ldu32(qp + 8 * HD);
        qa[kt][2] = ldu32(qp + 8);
        qa[kt][3] = ldu32(qp + 8 * HD + 8);
    }
    __syncthreads();

    const uint32_t kbase = smem_u32(&Ks[lane & 7][(lane >> 3) * 8]);
    const uint32_t vbase = smem_u32(&Vs[lane & 7][(lane >> 3) * 8]);

    float o[4][4] = {};   // d-tiles 0..3
    float o4[4]   = {};   // ones tile (row sums at col 32)

#pragma unroll 1
    for (int jc = 0; jc < 8; jc++) {
        // ---- S = Q K^T (16 x 32 chunk) ----
        float s[4][4] = {};
#pragma unroll
        for (int nt = 0; nt < 4; nt++) {
            unsigned kb[4];
            ldsm4(kb[0], kb[1], kb[2], kb[3],
                  kbase + (uint32_t)(jc * 32 + nt * 8) * 80);
            mma16(s[nt], qa[0], kb[0], kb[1]);
            mma16(s[nt], qa[1], kb[2], kb[3]);
        }

        // ---- P = 2^S as half2 A-fragments ----
        unsigned pa[2][4];
#pragma unroll
        for (int kt2 = 0; kt2 < 2; kt2++) {
            pa[kt2][0] = ex2h2(pack2(s[2 * kt2][0],     s[2 * kt2][1]));
            pa[kt2][1] = ex2h2(pack2(s[2 * kt2][2],     s[2 * kt2][3]));
            pa[kt2][2] = ex2h2(pack2(s[2 * kt2 + 1][0], s[2 * kt2 + 1][1]));
            pa[kt2][3] = ex2h2(pack2(s[2 * kt2 + 1][2], s[2 * kt2 + 1][3]));
        }

        // ---- O += P V  (5 d-tiles; tile 4 = ones -> row sums) ----
#pragma unroll
        for (int dt = 0; dt < 5; dt++) {
            unsigned vb[4];
            ldsm4(vb[0], vb[1], vb[2], vb[3],
                  vbase + (uint32_t)dt * 4224 + (uint32_t)jc * 64);
            float* op = (dt < 4) ? o[dt] : o4;
            mma16(op, pa[0], vb[0], vb[1]);
            mma16(op, pa[1], vb[2], vb[3]);
        }
    }

    // ---- finalize: row sum = o4[2hi] broadcast from tg==0 (col 32) ----
#pragma unroll
    for (int hi = 0; hi < 2; hi++) {
        const float sum = __shfl_sync(0xffffffffu, o4[2 * hi], lane & ~3);
        const float inv = __fdividef(1.0f, sum);
        const int l = half * 128 + warp * 16 + hi * 8 + g;
#pragma unroll
        for (int dt = 0; dt < 4; dt++) {
            const int c = ah * HD + dt * 8 + 2 * tg;
            *(unsigned*)(O + ((long)(b * LSEQ + l)) * CDIM + c) =
                pack2(o[dt][2 * hi] * inv, o[dt][2 * hi + 1] * inv);
        }
    }
}

// ============================================================================
// launch
// ============================================================================
extern "C" void kernel_launch(void* const* d_in, const int* in_sizes, int n_in,
                              void* d_out, int out_size)
{
    const float* x  = (const float*)d_in[0];
    const float* Wq = (const float*)d_in[1];
    const float* bq = (const float*)d_in[2];
    const float* Wk = (const float*)d_in[3];
    const float* bk = (const float*)d_in[4];
    const float* Wv = (const float*)d_in[5];
    const float* bv = (const float*)d_in[6];
    const float* Wp = (const float*)d_in[7];
    const float* bp = (const float*)d_in[8];

    __half *xh, *qp, *kp, *vp, *op, *wt;
    cudaGetSymbolAddress((void**)&xh, g_X);
    cudaGetSymbolAddress((void**)&qp, g_Q);
    cudaGetSymbolAddress((void**)&kp, g_K);
    cudaGetSymbolAddress((void**)&vp, g_V);
    cudaGetSymbolAddress((void**)&op, g_O);
    cudaGetSymbolAddress((void**)&wt, g_Wt);

    cudaFuncSetAttribute(gemm2_kernel<0>,
                         cudaFuncAttributeMaxDynamicSharedMemorySize, GEMM_SMEM_BYTES);
    cudaFuncSetAttribute(gemm2_kernel<1>,
                         cudaFuncAttributeMaxDynamicSharedMemorySize, GEMM_SMEM_BYTES);

    convert_x_kernel<<<(MROWS * CDIM) / (256 * 8), 256>>>(x, xh);
    transpose_w_kernel<<<dim3(4, 4, 4), 256>>>(Wq, Wk, Wv, Wp, wt);

    dim3 gqkv(6, MROWS / 128);
    gemm2_kernel<0><<<gqkv, 256, GEMM_SMEM_BYTES>>>(
        xh, wt, bq, bk, bv, qp, kp, vp);

    attn_f16_kernel<<<NBATCH * HEADS * 2, 256>>>(qp, kp, vp, op);

    dim3 gp(2, MROWS / 128);
    gemm2_kernel<1><<<gp, 256, GEMM_SMEM_BYTES>>>(
        op, wt + 3 * CDIM * CDIM, bp, bp, bp, d_out, d_out, d_out);
}

// round 10
// speedup vs baseline: 1.4541x; 1.4541x over previous
#include <cuda_runtime.h>
#include <cuda_fp16.h>
#include <cstdint>

// Problem constants
#define MROWS  131072      // N*H*W*L
#define CDIM   256
#define NBATCH 512
#define HEADS  8
#define HD     32
#define LSEQ   256
// QK scale folded with log2(e): exp(s/sqrt(32)) = 2^(s * QEXP_SCALE)
#define QEXP_SCALE (0.17677669529663689f * 1.4426950408889634f)

// -------- scratch (device globals) --------
__device__ __half g_X[(size_t)MROWS * CDIM];
__device__ __half g_Q[(size_t)NBATCH * HEADS * LSEQ * HD];
__device__ __half g_K[(size_t)NBATCH * HEADS * LSEQ * HD];
__device__ __half g_V[(size_t)NBATCH * HEADS * LSEQ * HD];
__device__ __half g_O[(size_t)MROWS * CDIM];
__device__ __half g_Wt[4 * CDIM * CDIM];   // [w][n][k] = W_w[k][n] as half

// -------- helpers --------
__device__ __forceinline__ void mma16(float c[4], const unsigned a[4],
                                      unsigned b0, unsigned b1) {
    asm volatile(
        "mma.sync.aligned.m16n8k16.row.col.f32.f16.f16.f32 "
        "{%0,%1,%2,%3}, {%4,%5,%6,%7}, {%8,%9}, {%0,%1,%2,%3};"
        : "+f"(c[0]), "+f"(c[1]), "+f"(c[2]), "+f"(c[3])
        : "r"(a[0]), "r"(a[1]), "r"(a[2]), "r"(a[3]), "r"(b0), "r"(b1));
}
__device__ __forceinline__ unsigned pack2(float lo, float hi) {
    __half2 h = __floats2half2_rn(lo, hi);
    return *reinterpret_cast<unsigned*>(&h);
}
__device__ __forceinline__ unsigned ex2h2(unsigned x) {
    unsigned r;
    asm("ex2.approx.f16x2 %0, %1;" : "=r"(r) : "r"(x));
    return r;
}
__device__ __forceinline__ uint32_t smem_u32(const void* p) {
    uint32_t a;
    asm("{ .reg .u64 t; cvta.to.shared.u64 t, %1; cvt.u32.u64 %0, t; }"
        : "=r"(a) : "l"(p));
    return a;
}
__device__ __forceinline__ void ldsm4(unsigned& r0, unsigned& r1,
                                      unsigned& r2, unsigned& r3, uint32_t a) {
    asm volatile("ldmatrix.sync.aligned.m8n8.x4.shared.b16 {%0,%1,%2,%3}, [%4];"
                 : "=r"(r0), "=r"(r1), "=r"(r2), "=r"(r3) : "r"(a));
}
__device__ __forceinline__ void ldsm4t(unsigned& r0, unsigned& r1,
                                       unsigned& r2, unsigned& r3, uint32_t a) {
    asm volatile("ldmatrix.sync.aligned.m8n8.x4.trans.shared.b16 {%0,%1,%2,%3}, [%4];"
                 : "=r"(r0), "=r"(r1), "=r"(r2), "=r"(r3) : "r"(a));
}
__device__ __forceinline__ void ldsm2t(unsigned& r0, unsigned& r1, uint32_t a) {
    asm volatile("ldmatrix.sync.aligned.m8n8.x2.trans.shared.b16 {%0,%1}, [%2];"
                 : "=r"(r0), "=r"(r1) : "r"(a));
}
__device__ __forceinline__ void cpasync16(uint32_t dst, const void* src) {
    asm volatile("cp.async.cg.shared.global [%0], [%1], 16;"
                 :: "r"(dst), "l"(src));
}

// ============================================================================
// pre-kernels: convert X to half; build Wt[w][n][k] = W_w[k][n] half
// ============================================================================
__global__ __launch_bounds__(256) void convert_x_kernel(
    const float* __restrict__ x, __half* __restrict__ xh)
{
    const size_t i = ((size_t)blockIdx.x * 256 + threadIdx.x) * 8;
    const float4 a = *(const float4*)(x + i);
    const float4 b = *(const float4*)(x + i + 4);
    uint4 v;
    v.x = pack2(a.x, a.y); v.y = pack2(a.z, a.w);
    v.z = pack2(b.x, b.y); v.w = pack2(b.z, b.w);
    *(uint4*)(xh + i) = v;
}

__global__ __launch_bounds__(256) void transpose_w_kernel(
    const float* __restrict__ W0, const float* __restrict__ W1,
    const float* __restrict__ W2, const float* __restrict__ W3,
    __half* __restrict__ Wt)
{
    __shared__ float tile[64][65];
    const int w  = blockIdx.z;
    const int k0 = blockIdx.x * 64;
    const int n0 = blockIdx.y * 64;
    const float* W = w == 0 ? W0 : (w == 1 ? W1 : (w == 2 ? W2 : W3));
    const int t = threadIdx.x;
    for (int i = t; i < 4096; i += 256) {
        const int r = i >> 6, c = i & 63;
        tile[c][r] = W[(k0 + r) * CDIM + n0 + c];
    }
    __syncthreads();
    for (int i = t; i < 4096; i += 256) {
        const int r = i >> 6, c = i & 63;
        Wt[(size_t)w * CDIM * CDIM + (n0 + r) * CDIM + k0 + c] = __float2half(tile[r][c]);
    }
}

// ============================================================================
// half GEMM (round-5 design, unchanged): cp.async double-buffered, ldmatrix,
// BM=128 BN=128 BK=64, 2 CTA/SM. MODE 0 Q-output pre-scaled by QEXP_SCALE.
// ============================================================================
#define GST 72
#define XS_HALFS (128 * GST)
#define GEMM_SMEM_BYTES (4 * XS_HALFS * 2)

template <int MODE>
__global__ __launch_bounds__(256, 2) void gemm2_kernel(
    const __half* __restrict__ X, const __half* __restrict__ Wt4,
    const float* __restrict__ b0p, const float* __restrict__ b1p,
    const float* __restrict__ b2p,
    void* __restrict__ o0, void* __restrict__ o1, void* __restrict__ o2)
{
    extern __shared__ __half smh[];
    const uint32_t sb = smem_u32(smh);

    const int t    = threadIdx.x;
    const int lane = t & 31;
    const int wid  = t >> 5;
    const int g    = lane >> 2;
    const int tg   = lane & 3;

    int widx = 0, nx = blockIdx.x;
    if (MODE == 0) { widx = nx >> 1; nx &= 1; }
    const int  n0 = nx * 128;
    const long m0 = (long)blockIdx.y * 128;
    const __half* Wt   = Wt4 + (size_t)widx * CDIM * CDIM;
    const float*  bias = widx == 0 ? b0p : (widx == 1 ? b1p : b2p);
    const float   osc  = (MODE == 0 && widx == 0) ? QEXP_SCALE : 1.0f;

    const int sr  = t >> 3;
    const int sc8 = (t & 7) * 8;

    auto issue = [&](int kb, int buf) {
        const __half* xs = X  + ((m0 + sr) << 8) + kb * 64 + sc8;
        const __half* ws = Wt + ((n0 + sr) << 8) + kb * 64 + sc8;
        const uint32_t xd = sb + (uint32_t)(buf * XS_HALFS + sr * GST + sc8) * 2;
        const uint32_t wd = sb + (uint32_t)((2 + buf) * XS_HALFS + sr * GST + sc8) * 2;
#pragma unroll
        for (int i = 0; i < 4; i++) {
            cpasync16(xd + i * 32 * GST * 2, xs + (i << 13));
            cpasync16(wd + i * 32 * GST * 2, ws + (i << 13));
        }
    };

    float acc[4][4][4] = {};

    const int m0w = (wid & 1) * 64;
    const int n0w = (wid >> 1) * 32;
    const int rr  = lane & 7;
    const int blk = lane >> 3;
    const int arow = m0w + (blk & 1) * 8 + rr;
    const int acol = (blk & 2) * 4;
    const int brow = n0w + ((blk & 2) ? 8 : 0) + rr;
    const int bcol = (blk & 1) * 8;

    issue(0, 0);
    asm volatile("cp.async.commit_group;");

#pragma unroll 1
    for (int kb = 0; kb < 4; kb++) {
        if (kb < 3) {
            issue(kb + 1, (kb + 1) & 1);
            asm volatile("cp.async.commit_group;");
            asm volatile("cp.async.wait_group 1;");
        } else {
            asm volatile("cp.async.wait_group 0;");
        }
        __syncthreads();

        const int buf = kb & 1;
        const uint32_t xbase = sb + (uint32_t)(buf * XS_HALFS) * 2;
        const uint32_t bbase = sb + (uint32_t)((2 + buf) * XS_HALFS) * 2;

#pragma unroll
        for (int kt = 0; kt < 4; kt++) {
            unsigned br[2][4];
#pragma unroll
            for (int nt2 = 0; nt2 < 2; nt2++)
                ldsm4(br[nt2][0], br[nt2][1], br[nt2][2], br[nt2][3],
                      bbase + (uint32_t)((brow + nt2 * 16) * GST + kt * 16 + bcol) * 2);
            unsigned ar[4][4];
#pragma unroll
            for (int mt = 0; mt < 4; mt++)
                ldsm4(ar[mt][0], ar[mt][1], ar[mt][2], ar[mt][3],
                      xbase + (uint32_t)((arow + mt * 16) * GST + kt * 16 + acol) * 2);
#pragma unroll
            for (int mt = 0; mt < 4; mt++) {
#pragma unroll
                for (int nt2 = 0; nt2 < 2; nt2++) {
                    mma16(acc[mt][nt2 * 2],     ar[mt], br[nt2][0], br[nt2][1]);
                    mma16(acc[mt][nt2 * 2 + 1], ar[mt], br[nt2][2], br[nt2][3]);
                }
            }
        }
        __syncthreads();
    }

#pragma unroll
    for (int mt = 0; mt < 4; mt++) {
#pragma unroll
        for (int hi = 0; hi < 2; hi++) {
            const long row = m0 + m0w + mt * 16 + hi * 8 + g;
#pragma unroll
            for (int nt = 0; nt < 4; nt++) {
                const int c = n0 + n0w + nt * 8 + 2 * tg;
                const float v0 = (acc[mt][nt][2 * hi]     + bias[c])     * osc;
                const float v1 = (acc[mt][nt][2 * hi + 1] + bias[c + 1]) * osc;
                if (MODE == 0) {
                    const long bb = row >> 8;
                    const int  l  = (int)(row & 255);
                    const int  ah = c >> 5;
                    const int  d  = c & 31;
                    __half* out = (__half*)(widx == 0 ? o0 : (widx == 1 ? o1 : o2));
                    *(unsigned*)(out + (((bb * HEADS + ah) * LSEQ + l) << 5) + d) = pack2(v0, v1);
                } else {
                    float2 v; v.x = v0; v.y = v1;
                    *(float2*)((float*)o0 + row * CDIM + c) = v;
                }
            }
        }
    }
}

// ============================================================================
// fp16 Attention v6: round-7 hot loop + cp.async prologue.
//   Q/K/V all staged row-major [256][40] via cp.async (12 LDGSTS/thread).
//   V transpose ELIMINATED: PV B-fragments via ldmatrix.x4.trans on row-major
//   V. Ones-COLUMN (cols 32-39) gives free row sums through an x2.trans tile.
//   Q fragments via ldmatrix from smem. 32 q-rows/warp, 2 CTA/SM, grid 4096.
// ============================================================================
__global__ __launch_bounds__(256, 2) void attn_f16_kernel(
    const __half* __restrict__ Q, const __half* __restrict__ K,
    const __half* __restrict__ V, __half* __restrict__ O)
{
    __shared__ __half Qs[LSEQ][40];
    __shared__ __half Ks[LSEQ][40];
    __shared__ __half Vs[LSEQ][40];   // cols 32-39: ones column + zeros

    const int t    = threadIdx.x;
    const int lane = t & 31;
    const int warp = t >> 5;
    const int g    = lane >> 2;
    const int tg   = lane & 3;

    const int  bh = blockIdx.x;
    const int  b  = bh >> 3;
    const int  ah = bh & 7;
    const __half* Qg = Q + (long)bh * LSEQ * HD;
    const __half* Kg = K + (long)bh * LSEQ * HD;
    const __half* Vg = V + (long)bh * LSEQ * HD;

    // ---- cp.async staging: 4 threads per 64B row ----
    const int sr = t >> 2;            // 0..63
    const int sc = (t & 3) * 8;       // half offset within row
    const uint32_t sq = smem_u32(&Qs[0][0]);
    const uint32_t sk = smem_u32(&Ks[0][0]);
    const uint32_t sv = smem_u32(&Vs[0][0]);
#pragma unroll
    for (int p = 0; p < 4; p++) {
        const int r = sr + p * 64;
        cpasync16(sq + (uint32_t)(r * 80 + sc * 2), Qg + r * HD + sc);
        cpasync16(sk + (uint32_t)(r * 80 + sc * 2), Kg + r * HD + sc);
        cpasync16(sv + (uint32_t)(r * 80 + sc * 2), Vg + r * HD + sc);
    }
    asm volatile("cp.async.commit_group;");

    // ones column: Vs[key][32] = 1, [33..39] = 0 (independent bytes)
    {
        const uint4 onev = {0x00003C00u, 0u, 0u, 0u};
        *(uint4*)&Vs[t][32] = onev;
    }
    asm volatile("cp.async.wait_group 0;" ::: "memory");
    __syncthreads();

    // ---- Q A-fragments via ldmatrix (one x4 per (mt,kt)) ----
    const uint32_t qbase = smem_u32(&Qs[warp * 32 + (lane & 15)][(lane >> 4) * 8]);
    unsigned qa[2][2][4];   // [kt][mt][reg]
#pragma unroll
    for (int mt = 0; mt < 2; mt++)
#pragma unroll
        for (int kt = 0; kt < 2; kt++)
            ldsm4(qa[kt][mt][0], qa[kt][mt][1], qa[kt][mt][2], qa[kt][mt][3],
                  qbase + (uint32_t)(mt * 16 * 80 + kt * 32));

    const uint32_t kbase = smem_u32(&Ks[lane & 7][(lane >> 3) * 8]);
    const uint32_t vb4   = smem_u32(&Vs[lane & 15][(lane >> 4) * 8]);
    const uint32_t vb2   = smem_u32(&Vs[lane & 15][32]);

    float o[2][4][4] = {};   // [mt][dt][reg]
    float o4[2][4]   = {};   // ones tile (row sums at col 32)

#pragma unroll 1
    for (int jc = 0; jc < 8; jc++) {
        // ---- S = Q K^T (32 x 32 chunk) ----
        float s[2][4][4] = {};
#pragma unroll
        for (int nt = 0; nt < 4; nt++) {
            unsigned kb[4];
            ldsm4(kb[0], kb[1], kb[2], kb[3],
                  kbase + (uint32_t)(jc * 32 + nt * 8) * 80);
            mma16(s[0][nt], qa[0][0], kb[0], kb[1]);
            mma16(s[0][nt], qa[1][0], kb[2], kb[3]);
            mma16(s[1][nt], qa[0][1], kb[0], kb[1]);
            mma16(s[1][nt], qa[1][1], kb[2], kb[3]);
        }

        // ---- P = 2^S as half2 A-fragments ----
        unsigned pa[2][2][4];   // [ks][mt][reg]
#pragma unroll
        for (int ks = 0; ks < 2; ks++)
#pragma unroll
            for (int mt = 0; mt < 2; mt++) {
                pa[ks][mt][0] = ex2h2(pack2(s[mt][2 * ks][0],     s[mt][2 * ks][1]));
                pa[ks][mt][1] = ex2h2(pack2(s[mt][2 * ks][2],     s[mt][2 * ks][3]));
                pa[ks][mt][2] = ex2h2(pack2(s[mt][2 * ks + 1][0], s[mt][2 * ks + 1][1]));
                pa[ks][mt][3] = ex2h2(pack2(s[mt][2 * ks + 1][2], s[mt][2 * ks + 1][3]));
            }

        // ---- O += P V : B-fragments via ldmatrix.trans on row-major V ----
#pragma unroll
        for (int ks = 0; ks < 2; ks++) {
            const uint32_t off = (uint32_t)(jc * 32 + ks * 16) * 80;
            unsigned v01[4], v23[4], v4[2];
            ldsm4t(v01[0], v01[1], v01[2], v01[3], vb4 + off);
            ldsm4t(v23[0], v23[1], v23[2], v23[3], vb4 + off + 32);
            ldsm2t(v4[0], v4[1], vb2 + off);
#pragma unroll
            for (int mt = 0; mt < 2; mt++) {
                mma16(o[mt][0], pa[ks][mt], v01[0], v01[1]);
                mma16(o[mt][1], pa[ks][mt], v01[2], v01[3]);
                mma16(o[mt][2], pa[ks][mt], v23[0], v23[1]);
                mma16(o[mt][3], pa[ks][mt], v23[2], v23[3]);
                mma16(o4[mt],   pa[ks][mt], v4[0],  v4[1]);
            }
        }
    }

    // ---- finalize: row sum = o4[mt][2hi] broadcast from tg==0 (col 32) ----
#pragma unroll
    for (int mt = 0; mt < 2; mt++) {
#pragma unroll
        for (int hi = 0; hi < 2; hi++) {
            const float sum = __shfl_sync(0xffffffffu, o4[mt][2 * hi], lane & ~3);
            const float inv = __fdividef(1.0f, sum);
            const int l = warp * 32 + mt * 16 + hi * 8 + g;
#pragma unroll
            for (int dt = 0; dt < 4; dt++) {
                const int c = ah * HD + dt * 8 + 2 * tg;
                *(unsigned*)(O + ((long)(b * LSEQ + l)) * CDIM + c) =
                    pack2(o[mt][dt][2 * hi] * inv, o[mt][dt][2 * hi + 1] * inv);
            }
        }
    }
}

// ============================================================================
// launch
// ============================================================================
extern "C" void kernel_launch(void* const* d_in, const int* in_sizes, int n_in,
                              void* d_out, int out_size)
{
    const float* x  = (const float*)d_in[0];
    const float* Wq = (const float*)d_in[1];
    const float* bq = (const float*)d_in[2];
    const float* Wk = (const float*)d_in[3];
    const float* bk = (const float*)d_in[4];
    const float* Wv = (const float*)d_in[5];
    const float* bv = (const float*)d_in[6];
    const float* Wp = (const float*)d_in[7];
    const float* bp = (const float*)d_in[8];

    __half *xh, *qp, *kp, *vp, *op, *wt;
    cudaGetSymbolAddress((void**)&xh, g_X);
    cudaGetSymbolAddress((void**)&qp, g_Q);
    cudaGetSymbolAddress((void**)&kp, g_K);
    cudaGetSymbolAddress((void**)&vp, g_V);
    cudaGetSymbolAddress((void**)&op, g_O);
    cudaGetSymbolAddress((void**)&wt, g_Wt);

    cudaFuncSetAttribute(gemm2_kernel<0>,
                         cudaFuncAttributeMaxDynamicSharedMemorySize, GEMM_SMEM_BYTES);
    cudaFuncSetAttribute(gemm2_kernel<1>,
                         cudaFuncAttributeMaxDynamicSharedMemorySize, GEMM_SMEM_BYTES);

    convert_x_kernel<<<(MROWS * CDIM) / (256 * 8), 256>>>(x, xh);
    transpose_w_kernel<<<dim3(4, 4, 4), 256>>>(Wq, Wk, Wv, Wp, wt);

    dim3 gqkv(6, MROWS / 128);
    gemm2_kernel<0><<<gqkv, 256, GEMM_SMEM_BYTES>>>(
        xh, wt, bq, bk, bv, qp, kp, vp);

    attn_f16_kernel<<<NBATCH * HEADS, 256>>>(qp, kp, vp, op);

    dim3 gp(2, MROWS / 128);
    gemm2_kernel<1><<<gp, 256, GEMM_SMEM_BYTES>>>(
        op, wt + 3 * CDIM * CDIM, bp, bp, bp, d_out, d_out, d_out);
}

// round 11
// speedup vs baseline: 1.4769x; 1.0157x over previous
#include <cuda_runtime.h>
#include <cuda_fp16.h>
#include <cstdint>

// Problem constants
#define MROWS  131072      // N*H*W*L
#define CDIM   256
#define NBATCH 512
#define HEADS  8
#define HD     32
#define LSEQ   256
// QK scale folded with log2(e): exp(s/sqrt(32)) = 2^(s * QEXP_SCALE)
#define QEXP_SCALE (0.17677669529663689f * 1.4426950408889634f)

// -------- scratch (device globals) --------
__device__ __half g_X[(size_t)MROWS * CDIM];
__device__ __half g_Q[(size_t)NBATCH * HEADS * LSEQ * HD];
__device__ __half g_K[(size_t)NBATCH * HEADS * LSEQ * HD];
__device__ __half g_V[(size_t)NBATCH * HEADS * LSEQ * HD];
__device__ __half g_O[(size_t)MROWS * CDIM];
__device__ __half g_Wt[4 * CDIM * CDIM];   // [w][n][k] = W_w[k][n] as half

// -------- helpers --------
__device__ __forceinline__ void mma16(float c[4], const unsigned a[4],
                                      unsigned b0, unsigned b1) {
    asm volatile(
        "mma.sync.aligned.m16n8k16.row.col.f32.f16.f16.f32 "
        "{%0,%1,%2,%3}, {%4,%5,%6,%7}, {%8,%9}, {%0,%1,%2,%3};"
        : "+f"(c[0]), "+f"(c[1]), "+f"(c[2]), "+f"(c[3])
        : "r"(a[0]), "r"(a[1]), "r"(a[2]), "r"(a[3]), "r"(b0), "r"(b1));
}
__device__ __forceinline__ unsigned pack2(float lo, float hi) {
    __half2 h = __floats2half2_rn(lo, hi);
    return *reinterpret_cast<unsigned*>(&h);
}
__device__ __forceinline__ unsigned ex2h2(unsigned x) {
    unsigned r;
    asm("ex2.approx.f16x2 %0, %1;" : "=r"(r) : "r"(x));
    return r;
}
__device__ __forceinline__ uint32_t smem_u32(const void* p) {
    uint32_t a;
    asm("{ .reg .u64 t; cvta.to.shared.u64 t, %1; cvt.u32.u64 %0, t; }"
        : "=r"(a) : "l"(p));
    return a;
}
__device__ __forceinline__ void ldsm4(unsigned& r0, unsigned& r1,
                                      unsigned& r2, unsigned& r3, uint32_t a) {
    asm volatile("ldmatrix.sync.aligned.m8n8.x4.shared.b16 {%0,%1,%2,%3}, [%4];"
                 : "=r"(r0), "=r"(r1), "=r"(r2), "=r"(r3) : "r"(a));
}
__device__ __forceinline__ void ldsm4t(unsigned& r0, unsigned& r1,
                                       unsigned& r2, unsigned& r3, uint32_t a) {
    asm volatile("ldmatrix.sync.aligned.m8n8.x4.trans.shared.b16 {%0,%1,%2,%3}, [%4];"
                 : "=r"(r0), "=r"(r1), "=r"(r2), "=r"(r3) : "r"(a));
}
__device__ __forceinline__ void ldsm2t(unsigned& r0, unsigned& r1, uint32_t a) {
    asm volatile("ldmatrix.sync.aligned.m8n8.x2.trans.shared.b16 {%0,%1}, [%2];"
                 : "=r"(r0), "=r"(r1) : "r"(a));
}
__device__ __forceinline__ void cpasync16(uint32_t dst, const void* src) {
    asm volatile("cp.async.cg.shared.global [%0], [%1], 16;"
                 :: "r"(dst), "l"(src));
}

// ============================================================================
// prep kernel: convert X to half (blocks 0..16383) and build
// Wt[w][n][k] = W_w[k][n] half (blocks 16384..16447) in ONE launch.
// ============================================================================
__global__ __launch_bounds__(256) void prep_kernel(
    const float* __restrict__ x, __half* __restrict__ xh,
    const float* __restrict__ W0, const float* __restrict__ W1,
    const float* __restrict__ W2, const float* __restrict__ W3,
    __half* __restrict__ Wt)
{
    __shared__ float tile[64][65];
    const int t = threadIdx.x;
    if (blockIdx.x < 16384) {
        const size_t i = ((size_t)blockIdx.x * 256 + t) * 8;
        const float4 a = *(const float4*)(x + i);
        const float4 b = *(const float4*)(x + i + 4);
        uint4 v;
        v.x = pack2(a.x, a.y); v.y = pack2(a.z, a.w);
        v.z = pack2(b.x, b.y); v.w = pack2(b.z, b.w);
        *(uint4*)(xh + i) = v;
    } else {
        const int bid = blockIdx.x - 16384;          // 0..63
        const int w  = bid >> 4;
        const int k0 = ((bid >> 2) & 3) * 64;
        const int n0 = (bid & 3) * 64;
        const float* W = w == 0 ? W0 : (w == 1 ? W1 : (w == 2 ? W2 : W3));
        for (int i = t; i < 4096; i += 256) {
            const int r = i >> 6, c = i & 63;
            tile[c][r] = W[(k0 + r) * CDIM + n0 + c];
        }
        __syncthreads();
        for (int i = t; i < 4096; i += 256) {
            const int r = i >> 6, c = i & 63;
            Wt[(size_t)w * CDIM * CDIM + (n0 + r) * CDIM + k0 + c] =
                __float2half(tile[r][c]);
        }
    }
}

// ============================================================================
// half GEMM, 3-STAGE cp.async pipeline: loads for kb+2 issued two compute
// phases ahead -> DRAM latency fully hidden. BM=128 BN=128 BK=64, 8 warps
// 2m x 4n (warp 64x32), ldmatrix fragments, 2 CTA/SM (110.6KB smem each).
// MODE 0: half out, head-split scatter, Q pre-scaled by QEXP_SCALE.
// MODE 1: fp32 out row-major.
// ============================================================================
#define GST 72
#define XS_HALFS (128 * GST)                    // one X or W tile: 9216 halfs
#define GEMM_SMEM_BYTES (6 * XS_HALFS * 2)      // 3 stages x (X+W) = 110592 B

template <int MODE>
__global__ __launch_bounds__(256, 2) void gemm2_kernel(
    const __half* __restrict__ X, const __half* __restrict__ Wt4,
    const float* __restrict__ b0p, const float* __restrict__ b1p,
    const float* __restrict__ b2p,
    void* __restrict__ o0, void* __restrict__ o1, void* __restrict__ o2)
{
    extern __shared__ __half smh[];
    const uint32_t sb = smem_u32(smh);

    const int t    = threadIdx.x;
    const int lane = t & 31;
    const int wid  = t >> 5;
    const int g    = lane >> 2;
    const int tg   = lane & 3;

    int widx = 0, nx = blockIdx.x;
    if (MODE == 0) { widx = nx >> 1; nx &= 1; }
    const int  n0 = nx * 128;
    const long m0 = (long)blockIdx.y * 128;
    const __half* Wt   = Wt4 + (size_t)widx * CDIM * CDIM;
    const float*  bias = widx == 0 ? b0p : (widx == 1 ? b1p : b2p);
    const float   osc  = (MODE == 0 && widx == 0) ? QEXP_SCALE : 1.0f;

    const int sr  = t >> 3;
    const int sc8 = (t & 7) * 8;

    auto issue = [&](int kb, int buf) {
        const __half* xs = X  + ((m0 + sr) << 8) + kb * 64 + sc8;
        const __half* ws = Wt + ((n0 + sr) << 8) + kb * 64 + sc8;
        const uint32_t xd = sb + (uint32_t)(buf * 2 * XS_HALFS + sr * GST + sc8) * 2;
        const uint32_t wd = sb + (uint32_t)((buf * 2 + 1) * XS_HALFS + sr * GST + sc8) * 2;
#pragma unroll
        for (int i = 0; i < 4; i++) {
            cpasync16(xd + i * 32 * GST * 2, xs + (i << 13));
            cpasync16(wd + i * 32 * GST * 2, ws + (i << 13));
        }
    };

    float acc[4][4][4] = {};

    const int m0w = (wid & 1) * 64;
    const int n0w = (wid >> 1) * 32;
    const int rr  = lane & 7;
    const int blk = lane >> 3;
    const int arow = m0w + (blk & 1) * 8 + rr;
    const int acol = (blk & 2) * 4;
    const int brow = n0w + ((blk & 2) ? 8 : 0) + rr;
    const int bcol = (blk & 1) * 8;

    issue(0, 0);
    asm volatile("cp.async.commit_group;");
    issue(1, 1);
    asm volatile("cp.async.commit_group;");

#pragma unroll 1
    for (int kb = 0; kb < 4; kb++) {
        if (kb < 2) {
            issue(kb + 2, (kb + 2) % 3);
            asm volatile("cp.async.commit_group;");
        }
        // groups outstanding after issue: kb<2 -> {kb,kb+1,kb+2}; kb==2 -> {2,3}; kb==3 -> {3}
        if (kb < 2)       asm volatile("cp.async.wait_group 2;");
        else if (kb == 2) asm volatile("cp.async.wait_group 1;");
        else              asm volatile("cp.async.wait_group 0;");
        __syncthreads();

        const int buf = kb % 3;
        const uint32_t xbase = sb + (uint32_t)(buf * 2 * XS_HALFS) * 2;
        const uint32_t bbase = sb + (uint32_t)((buf * 2 + 1) * XS_HALFS) * 2;

#pragma unroll
        for (int kt = 0; kt < 4; kt++) {
            unsigned br[2][4];
#pragma unroll
            for (int nt2 = 0; nt2 < 2; nt2++)
                ldsm4(br[nt2][0], br[nt2][1], br[nt2][2], br[nt2][3],
                      bbase + (uint32_t)((brow + nt2 * 16) * GST + kt * 16 + bcol) * 2);
            unsigned ar[4][4];
#pragma unroll
            for (int mt = 0; mt < 4; mt++)
                ldsm4(ar[mt][0], ar[mt][1], ar[mt][2], ar[mt][3],
                      xbase + (uint32_t)((arow + mt * 16) * GST + kt * 16 + acol) * 2);
#pragma unroll
            for (int mt = 0; mt < 4; mt++) {
#pragma unroll
                for (int nt2 = 0; nt2 < 2; nt2++) {
                    mma16(acc[mt][nt2 * 2],     ar[mt], br[nt2][0], br[nt2][1]);
                    mma16(acc[mt][nt2 * 2 + 1], ar[mt], br[nt2][2], br[nt2][3]);
                }
            }
        }
        __syncthreads();
    }

#pragma unroll
    for (int mt = 0; mt < 4; mt++) {
#pragma unroll
        for (int hi = 0; hi < 2; hi++) {
            const long row = m0 + m0w + mt * 16 + hi * 8 + g;
#pragma unroll
            for (int nt = 0; nt < 4; nt++) {
                const int c = n0 + n0w + nt * 8 + 2 * tg;
                const float v0 = (acc[mt][nt][2 * hi]     + bias[c])     * osc;
                const float v1 = (acc[mt][nt][2 * hi + 1] + bias[c + 1]) * osc;
                if (MODE == 0) {
                    const long bb = row >> 8;
                    const int  l  = (int)(row & 255);
                    const int  ah = c >> 5;
                    const int  d  = c & 31;
                    __half* out = (__half*)(widx == 0 ? o0 : (widx == 1 ? o1 : o2));
                    *(unsigned*)(out + (((bb * HEADS + ah) * LSEQ + l) << 5) + d) = pack2(v0, v1);
                } else {
                    float2 v; v.x = v0; v.y = v1;
                    *(float2*)((float*)o0 + row * CDIM + c) = v;
                }
            }
        }
    }
}

// ============================================================================
// fp16 Attention v6 (round-10 winner, UNCHANGED): cp.async prologue,
// ldmatrix.trans V fragments, ones-column row sums, max-free exp2 softmax.
// ============================================================================
__global__ __launch_bounds__(256, 2) void attn_f16_kernel(
    const __half* __restrict__ Q, const __half* __restrict__ K,
    const __half* __restrict__ V, __half* __restrict__ O)
{
    __shared__ __half Qs[LSEQ][40];
    __shared__ __half Ks[LSEQ][40];
    __shared__ __half Vs[LSEQ][40];   // cols 32-39: ones column + zeros

    const int t    = threadIdx.x;
    const int lane = t & 31;
    const int warp = t >> 5;
    const int g    = lane >> 2;
    const int tg   = lane & 3;

    const int  bh = blockIdx.x;
    const int  b  = bh >> 3;
    const int  ah = bh & 7;
    const __half* Qg = Q + (long)bh * LSEQ * HD;
    const __half* Kg = K + (long)bh * LSEQ * HD;
    const __half* Vg = V + (long)bh * LSEQ * HD;

    // ---- cp.async staging: 4 threads per 64B row ----
    const int sr = t >> 2;
    const int sc = (t & 3) * 8;
    const uint32_t sq = smem_u32(&Qs[0][0]);
    const uint32_t sk = smem_u32(&Ks[0][0]);
    const uint32_t sv = smem_u32(&Vs[0][0]);
#pragma unroll
    for (int p = 0; p < 4; p++) {
        const int r = sr + p * 64;
        cpasync16(sq + (uint32_t)(r * 80 + sc * 2), Qg + r * HD + sc);
        cpasync16(sk + (uint32_t)(r * 80 + sc * 2), Kg + r * HD + sc);
        cpasync16(sv + (uint32_t)(r * 80 + sc * 2), Vg + r * HD + sc);
    }
    asm volatile("cp.async.commit_group;");

    {
        const uint4 onev = {0x00003C00u, 0u, 0u, 0u};
        *(uint4*)&Vs[t][32] = onev;
    }
    asm volatile("cp.async.wait_group 0;" ::: "memory");
    __syncthreads();

    // ---- Q A-fragments via ldmatrix ----
    const uint32_t qbase = smem_u32(&Qs[warp * 32 + (lane & 15)][(lane >> 4) * 8]);
    unsigned qa[2][2][4];
#pragma unroll
    for (int mt = 0; mt < 2; mt++)
#pragma unroll
        for (int kt = 0; kt < 2; kt++)
            ldsm4(qa[kt][mt][0], qa[kt][mt][1], qa[kt][mt][2], qa[kt][mt][3],
                  qbase + (uint32_t)(mt * 16 * 80 + kt * 32));

    const uint32_t kbase = smem_u32(&Ks[lane & 7][(lane >> 3) * 8]);
    const uint32_t vb4   = smem_u32(&Vs[lane & 15][(lane >> 4) * 8]);
    const uint32_t vb2   = smem_u32(&Vs[lane & 15][32]);

    float o[2][4][4] = {};
    float o4[2][4]   = {};

#pragma unroll 1
    for (int jc = 0; jc < 8; jc++) {
        float s[2][4][4] = {};
#pragma unroll
        for (int nt = 0; nt < 4; nt++) {
            unsigned kb[4];
            ldsm4(kb[0], kb[1], kb[2], kb[3],
                  kbase + (uint32_t)(jc * 32 + nt * 8) * 80);
            mma16(s[0][nt], qa[0][0], kb[0], kb[1]);
            mma16(s[0][nt], qa[1][0], kb[2], kb[3]);
            mma16(s[1][nt], qa[0][1], kb[0], kb[1]);
            mma16(s[1][nt], qa[1][1], kb[2], kb[3]);
        }

        unsigned pa[2][2][4];
#pragma unroll
        for (int ks = 0; ks < 2; ks++)
#pragma unroll
            for (int mt = 0; mt < 2; mt++) {
                pa[ks][mt][0] = ex2h2(pack2(s[mt][2 * ks][0],     s[mt][2 * ks][1]));
                pa[ks][mt][1] = ex2h2(pack2(s[mt][2 * ks][2],     s[mt][2 * ks][3]));
                pa[ks][mt][2] = ex2h2(pack2(s[mt][2 * ks + 1][0], s[mt][2 * ks + 1][1]));
                pa[ks][mt][3] = ex2h2(pack2(s[mt][2 * ks + 1][2], s[mt][2 * ks + 1][3]));
            }

#pragma unroll
        for (int ks = 0; ks < 2; ks++) {
            const uint32_t off = (uint32_t)(jc * 32 + ks * 16) * 80;
            unsigned v01[4], v23[4], v4[2];
            ldsm4t(v01[0], v01[1], v01[2], v01[3], vb4 + off);
            ldsm4t(v23[0], v23[1], v23[2], v23[3], vb4 + off + 32);
            ldsm2t(v4[0], v4[1], vb2 + off);
#pragma unroll
            for (int mt = 0; mt < 2; mt++) {
                mma16(o[mt][0], pa[ks][mt], v01[0], v01[1]);
                mma16(o[mt][1], pa[ks][mt], v01[2], v01[3]);
                mma16(o[mt][2], pa[ks][mt], v23[0], v23[1]);
                mma16(o[mt][3], pa[ks][mt], v23[2], v23[3]);
                mma16(o4[mt],   pa[ks][mt], v4[0],  v4[1]);
            }
        }
    }

#pragma unroll
    for (int mt = 0; mt < 2; mt++) {
#pragma unroll
        for (int hi = 0; hi < 2; hi++) {
            const float sum = __shfl_sync(0xffffffffu, o4[mt][2 * hi], lane & ~3);
            const float inv = __fdividef(1.0f, sum);
            const int l = warp * 32 + mt * 16 + hi * 8 + g;
#pragma unroll
            for (int dt = 0; dt < 4; dt++) {
                const int c = ah * HD + dt * 8 + 2 * tg;
                *(unsigned*)(O + ((long)(b * LSEQ + l)) * CDIM + c) =
                    pack2(o[mt][dt][2 * hi] * inv, o[mt][dt][2 * hi + 1] * inv);
            }
        }
    }
}

// ============================================================================
// launch
// ============================================================================
extern "C" void kernel_launch(void* const* d_in, const int* in_sizes, int n_in,
                              void* d_out, int out_size)
{
    const float* x  = (const float*)d_in[0];
    const float* Wq = (const float*)d_in[1];
    const float* bq = (const float*)d_in[2];
    const float* Wk = (const float*)d_in[3];
    const float* bk = (const float*)d_in[4];
    const float* Wv = (const float*)d_in[5];
    const float* bv = (const float*)d_in[6];
    const float* Wp = (const float*)d_in[7];
    const float* bp = (const float*)d_in[8];

    __half *xh, *qp, *kp, *vp, *op, *wt;
    cudaGetSymbolAddress((void**)&xh, g_X);
    cudaGetSymbolAddress((void**)&qp, g_Q);
    cudaGetSymbolAddress((void**)&kp, g_K);
    cudaGetSymbolAddress((void**)&vp, g_V);
    cudaGetSymbolAddress((void**)&op, g_O);
    cudaGetSymbolAddress((void**)&wt, g_Wt);

    cudaFuncSetAttribute(gemm2_kernel<0>,
                         cudaFuncAttributeMaxDynamicSharedMemorySize, GEMM_SMEM_BYTES);
    cudaFuncSetAttribute(gemm2_kernel<1>,
                         cudaFuncAttributeMaxDynamicSharedMemorySize, GEMM_SMEM_BYTES);

    prep_kernel<<<16384 + 64, 256>>>(x, xh, Wq, Wk, Wv, Wp, wt);

    dim3 gqkv(6, MROWS / 128);
    gemm2_kernel<0><<<gqkv, 256, GEMM_SMEM_BYTES>>>(
        xh, wt, bq, bk, bv, qp, kp, vp);

    attn_f16_kernel<<<NBATCH * HEADS, 256>>>(qp, kp, vp, op);

    dim3 gp(2, MROWS / 128);
    gemm2_kernel<1><<<gp, 256, GEMM_SMEM_BYTES>>>(
        op, wt + 3 * CDIM * CDIM, bp, bp, bp, d_out, d_out, d_out);
}

// round 12
// speedup vs baseline: 1.5390x; 1.0420x over previous
#include <cuda_runtime.h>
#include <cuda_fp16.h>
#include <cstdint>

// Problem constants
#define MROWS  131072      // N*H*W*L
#define CDIM   256
#define NBATCH 512
#define HEADS  8
#define HD     32
#define LSEQ   256
#define NMTILE (MROWS / 128)   // 1024 m-tiles
// QK scale folded with log2(e): exp(s/sqrt(32)) = 2^(s * QEXP_SCALE)
#define QEXP_SCALE (0.17677669529663689f * 1.4426950408889634f)

// -------- scratch (device globals) --------
__device__ __half g_X[(size_t)MROWS * CDIM];
__device__ __half g_Q[(size_t)NBATCH * HEADS * LSEQ * HD];
__device__ __half g_K[(size_t)NBATCH * HEADS * LSEQ * HD];
__device__ __half g_V[(size_t)NBATCH * HEADS * LSEQ * HD];
__device__ __half g_O[(size_t)MROWS * CDIM];
__device__ __half g_Wt[4 * CDIM * CDIM];   // [w][n][k] = W_w[k][n] as half

// -------- helpers --------
__device__ __forceinline__ void mma16(float c[4], const unsigned a[4],
                                      unsigned b0, unsigned b1) {
    asm volatile(
        "mma.sync.aligned.m16n8k16.row.col.f32.f16.f16.f32 "
        "{%0,%1,%2,%3}, {%4,%5,%6,%7}, {%8,%9}, {%0,%1,%2,%3};"
        : "+f"(c[0]), "+f"(c[1]), "+f"(c[2]), "+f"(c[3])
        : "r"(a[0]), "r"(a[1]), "r"(a[2]), "r"(a[3]), "r"(b0), "r"(b1));
}
__device__ __forceinline__ unsigned pack2(float lo, float hi) {
    __half2 h = __floats2half2_rn(lo, hi);
    return *reinterpret_cast<unsigned*>(&h);
}
__device__ __forceinline__ unsigned ex2h2(unsigned x) {
    unsigned r;
    asm("ex2.approx.f16x2 %0, %1;" : "=r"(r) : "r"(x));
    return r;
}
__device__ __forceinline__ uint32_t smem_u32(const void* p) {
    uint32_t a;
    asm("{ .reg .u64 t; cvta.to.shared.u64 t, %1; cvt.u32.u64 %0, t; }"
        : "=r"(a) : "l"(p));
    return a;
}
__device__ __forceinline__ void ldsm4(unsigned& r0, unsigned& r1,
                                      unsigned& r2, unsigned& r3, uint32_t a) {
    asm volatile("ldmatrix.sync.aligned.m8n8.x4.shared.b16 {%0,%1,%2,%3}, [%4];"
                 : "=r"(r0), "=r"(r1), "=r"(r2), "=r"(r3) : "r"(a));
}
__device__ __forceinline__ void ldsm4t(unsigned& r0, unsigned& r1,
                                       unsigned& r2, unsigned& r3, uint32_t a) {
    asm volatile("ldmatrix.sync.aligned.m8n8.x4.trans.shared.b16 {%0,%1,%2,%3}, [%4];"
                 : "=r"(r0), "=r"(r1), "=r"(r2), "=r"(r3) : "r"(a));
}
__device__ __forceinline__ void ldsm2t(unsigned& r0, unsigned& r1, uint32_t a) {
    asm volatile("ldmatrix.sync.aligned.m8n8.x2.trans.shared.b16 {%0,%1}, [%2];"
                 : "=r"(r0), "=r"(r1) : "r"(a));
}
__device__ __forceinline__ void cpasync16(uint32_t dst, const void* src) {
    asm volatile("cp.async.cg.shared.global [%0], [%1], 16;"
                 :: "r"(dst), "l"(src));
}

// ============================================================================
// prep kernel: convert X to half (blocks 0..16383) and build
// Wt[w][n][k] = W_w[k][n] half (blocks 16384..16447) in ONE launch.
// ============================================================================
__global__ __launch_bounds__(256) void prep_kernel(
    const float* __restrict__ x, __half* __restrict__ xh,
    const float* __restrict__ W0, const float* __restrict__ W1,
    const float* __restrict__ W2, const float* __restrict__ W3,
    __half* __restrict__ Wt)
{
    __shared__ float tile[64][65];
    const int t = threadIdx.x;
    if (blockIdx.x < 16384) {
        const size_t i = ((size_t)blockIdx.x * 256 + t) * 8;
        const float4 a = *(const float4*)(x + i);
        const float4 b = *(const float4*)(x + i + 4);
        uint4 v;
        v.x = pack2(a.x, a.y); v.y = pack2(a.z, a.w);
        v.z = pack2(b.x, b.y); v.w = pack2(b.z, b.w);
        *(uint4*)(xh + i) = v;
    } else {
        const int bid = blockIdx.x - 16384;          // 0..63
        const int w  = bid >> 4;
        const int k0 = ((bid >> 2) & 3) * 64;
        const int n0 = (bid & 3) * 64;
        const float* W = w == 0 ? W0 : (w == 1 ? W1 : (w == 2 ? W2 : W3));
        for (int i = t; i < 4096; i += 256) {
            const int r = i >> 6, c = i & 63;
            tile[c][r] = W[(k0 + r) * CDIM + n0 + c];
        }
        __syncthreads();
        for (int i = t; i < 4096; i += 256) {
            const int r = i >> 6, c = i & 63;
            Wt[(size_t)w * CDIM * CDIM + (n0 + r) * CDIM + k0 + c] =
                __float2half(tile[r][c]);
        }
    }
}

// ============================================================================
// PERSISTENT half GEMM, W-resident:
//   Each CTA stages its W slice [128n x 256k] into smem ONCE, then loops over
//   m-tiles (mt = blockIdx.y, += gridDim.y) streaming X with a 2-buffer
//   cp.async pipeline that runs CONTINUOUSLY across m-tiles (fill bubble paid
//   once per kernel). Per-kb load traffic halves (X only). Bias in registers.
//   BM=128 BN=128 BK=64, 8 warps 2m x 4n, ldmatrix, 2 CTA/SM (104.4KB smem).
// MODE 0: half out, head-split scatter, Q slice pre-scaled by QEXP_SCALE.
// MODE 1: fp32 out row-major.
// ============================================================================
#define GST 72
#define WST 264                                  // halfs per W row (256+8)
#define XS_HALFS (128 * GST)                     // 9216
#define WS_HALFS (128 * WST)                     // 33792
#define GEMM_SMEM_BYTES ((WS_HALFS + 2 * XS_HALFS) * 2)   // 104448

template <int MODE>
__global__ __launch_bounds__(256, 2) void gemm3_kernel(
    const __half* __restrict__ X, const __half* __restrict__ Wt4,
    const float* __restrict__ b0p, const float* __restrict__ b1p,
    const float* __restrict__ b2p,
    void* __restrict__ o0, void* __restrict__ o1, void* __restrict__ o2)
{
    extern __shared__ __half smh[];
    const uint32_t sb = smem_u32(smh);           // Ws at 0, X bufs after

    const int t    = threadIdx.x;
    const int lane = t & 31;
    const int wid  = t >> 5;
    const int g    = lane >> 2;
    const int tg   = lane & 3;

    int widx = 0, nx = blockIdx.x;
    if (MODE == 0) { widx = nx >> 1; nx &= 1; }
    const int  n0 = nx * 128;
    const __half* Wt   = Wt4 + (size_t)widx * CDIM * CDIM;
    const float*  bias = widx == 0 ? b0p : (widx == 1 ? b1p : b2p);
    const float   osc  = (MODE == 0 && widx == 0) ? QEXP_SCALE : 1.0f;

    // ---- stage W slice once: rows n0..n0+127, all K ----
#pragma unroll
    for (int i = 0; i < 16; i++) {
        const int j   = t + i * 256;
        const int r   = j >> 5;             // 0..127
        const int c16 = (j & 31) * 8;       // half offset
        cpasync16(sb + (uint32_t)(r * WST + c16) * 2,
                  Wt + (n0 + r) * CDIM + c16);
    }
    asm volatile("cp.async.commit_group;");

    // ---- warp tiling / fragment addressing ----
    const int m0w = (wid & 1) * 64;
    const int n0w = (wid >> 1) * 32;
    const int rr  = lane & 7;
    const int blk = lane >> 3;
    const int arow = m0w + (blk & 1) * 8 + rr;
    const int acol = (blk & 2) * 4;
    const int brow = n0w + ((blk & 2) ? 8 : 0) + rr;
    const int bcol = (blk & 1) * 8;

    // hoisted bias (columns fixed per thread across all m-tiles)
    float bv[4][2];
#pragma unroll
    for (int nt = 0; nt < 4; nt++) {
        const int c = n0 + n0w + nt * 8 + 2 * tg;
        bv[nt][0] = bias[c];
        bv[nt][1] = bias[c + 1];
    }

    // X staging map: 4 threads... sr = t>>3 (0..31), rows sr+p*32
    const int sr  = t >> 3;
    const int sc8 = (t & 7) * 8;
    auto issueX = [&](int mt, int kb, int buf) {
        const __half* xs = X + (((long)mt * 128 + sr) << 8) + kb * 64 + sc8;
        const uint32_t xd = sb + (uint32_t)(WS_HALFS + buf * XS_HALFS + sr * GST + sc8) * 2;
#pragma unroll
        for (int i = 0; i < 4; i++)
            cpasync16(xd + i * 32 * GST * 2, xs + (i << 13));
    };

    // wait for W before first compute (grouped with first X wait below)
    const int y0 = blockIdx.y;
    const int yS = gridDim.y;

    // pipeline iterators
    int mt_is = y0, kb_is = 0;
    issueX(mt_is, kb_is, 0);
    asm volatile("cp.async.commit_group;");
    if (++kb_is == 4) { kb_is = 0; mt_is += yS; }

    int it = 0;
#pragma unroll 1
    for (int mt = y0; mt < NMTILE; mt += yS) {
        float acc[4][4][4] = {};
#pragma unroll 1
        for (int kb = 0; kb < 4; kb++) {
            if (mt_is < NMTILE) {
                issueX(mt_is, kb_is, (it + 1) & 1);
                asm volatile("cp.async.commit_group;");
                if (++kb_is == 4) { kb_is = 0; mt_is += yS; }
                asm volatile("cp.async.wait_group 1;");
            } else {
                asm volatile("cp.async.wait_group 0;");
            }
            __syncthreads();

            const uint32_t xbase = sb + (uint32_t)(WS_HALFS + (it & 1) * XS_HALFS) * 2;

#pragma unroll
            for (int kt = 0; kt < 4; kt++) {
                unsigned br[2][4];
#pragma unroll
                for (int nt2 = 0; nt2 < 2; nt2++)
                    ldsm4(br[nt2][0], br[nt2][1], br[nt2][2], br[nt2][3],
                          sb + (uint32_t)((brow + nt2 * 16) * WST + kb * 64 + kt * 16 + bcol) * 2);
                unsigned ar[4][4];
#pragma unroll
                for (int mta = 0; mta < 4; mta++)
                    ldsm4(ar[mta][0], ar[mta][1], ar[mta][2], ar[mta][3],
                          xbase + (uint32_t)((arow + mta * 16) * GST + kt * 16 + acol) * 2);
#pragma unroll
                for (int mta = 0; mta < 4; mta++) {
#pragma unroll
                    for (int nt2 = 0; nt2 < 2; nt2++) {
                        mma16(acc[mta][nt2 * 2],     ar[mta], br[nt2][0], br[nt2][1]);
                        mma16(acc[mta][nt2 * 2 + 1], ar[mta], br[nt2][2], br[nt2][3]);
                    }
                }
            }
            __syncthreads();
            it++;
        }

        // ---- epilogue for this m-tile (overlaps in-flight next loads) ----
#pragma unroll
        for (int mta = 0; mta < 4; mta++) {
#pragma unroll
            for (int hi = 0; hi < 2; hi++) {
                const long row = (long)mt * 128 + m0w + mta * 16 + hi * 8 + g;
#pragma unroll
                for (int nt = 0; nt < 4; nt++) {
                    const int c = n0 + n0w + nt * 8 + 2 * tg;
                    const float v0 = (acc[mta][nt][2 * hi]     + bv[nt][0]) * osc;
                    const float v1 = (acc[mta][nt][2 * hi + 1] + bv[nt][1]) * osc;
                    if (MODE == 0) {
                        const long bb = row >> 8;
                        const int  l  = (int)(row & 255);
                        const int  ah = c >> 5;
                        const int  d  = c & 31;
                        __half* out = (__half*)(widx == 0 ? o0 : (widx == 1 ? o1 : o2));
                        *(unsigned*)(out + (((bb * HEADS + ah) * LSEQ + l) << 5) + d) = pack2(v0, v1);
                    } else {
                        float2 v; v.x = v0; v.y = v1;
                        *(float2*)((float*)o0 + row * CDIM + c) = v;
                    }
                }
            }
        }
    }
}

// ============================================================================
// fp16 Attention v6 (round-10 winner, UNCHANGED): cp.async prologue,
// ldmatrix.trans V fragments, ones-column row sums, max-free exp2 softmax.
// ============================================================================
__global__ __launch_bounds__(256, 2) void attn_f16_kernel(
    const __half* __restrict__ Q, const __half* __restrict__ K,
    const __half* __restrict__ V, __half* __restrict__ O)
{
    __shared__ __half Qs[LSEQ][40];
    __shared__ __half Ks[LSEQ][40];
    __shared__ __half Vs[LSEQ][40];   // cols 32-39: ones column + zeros

    const int t    = threadIdx.x;
    const int lane = t & 31;
    const int warp = t >> 5;
    const int g    = lane >> 2;
    const int tg   = lane & 3;

    const int  bh = blockIdx.x;
    const int  b  = bh >> 3;
    const int  ah = bh & 7;
    const __half* Qg = Q + (long)bh * LSEQ * HD;
    const __half* Kg = K + (long)bh * LSEQ * HD;
    const __half* Vg = V + (long)bh * LSEQ * HD;

    const int sr = t >> 2;
    const int sc = (t & 3) * 8;
    const uint32_t sq = smem_u32(&Qs[0][0]);
    const uint32_t sk = smem_u32(&Ks[0][0]);
    const uint32_t sv = smem_u32(&Vs[0][0]);
#pragma unroll
    for (int p = 0; p < 4; p++) {
        const int r = sr + p * 64;
        cpasync16(sq + (uint32_t)(r * 80 + sc * 2), Qg + r * HD + sc);
        cpasync16(sk + (uint32_t)(r * 80 + sc * 2), Kg + r * HD + sc);
        cpasync16(sv + (uint32_t)(r * 80 + sc * 2), Vg + r * HD + sc);
    }
    asm volatile("cp.async.commit_group;");

    {
        const uint4 onev = {0x00003C00u, 0u, 0u, 0u};
        *(uint4*)&Vs[t][32] = onev;
    }
    asm volatile("cp.async.wait_group 0;" ::: "memory");
    __syncthreads();

    const uint32_t qbase = smem_u32(&Qs[warp * 32 + (lane & 15)][(lane >> 4) * 8]);
    unsigned qa[2][2][4];
#pragma unroll
    for (int mt = 0; mt < 2; mt++)
#pragma unroll
        for (int kt = 0; kt < 2; kt++)
            ldsm4(qa[kt][mt][0], qa[kt][mt][1], qa[kt][mt][2], qa[kt][mt][3],
                  qbase + (uint32_t)(mt * 16 * 80 + kt * 32));

    const uint32_t kbase = smem_u32(&Ks[lane & 7][(lane >> 3) * 8]);
    const uint32_t vb4   = smem_u32(&Vs[lane & 15][(lane >> 4) * 8]);
    const uint32_t vb2   = smem_u32(&Vs[lane & 15][32]);

    float o[2][4][4] = {};
    float o4[2][4]   = {};

#pragma unroll 1
    for (int jc = 0; jc < 8; jc++) {
        float s[2][4][4] = {};
#pragma unroll
        for (int nt = 0; nt < 4; nt++) {
            unsigned kb[4];
            ldsm4(kb[0], kb[1], kb[2], kb[3],
                  kbase + (uint32_t)(jc * 32 + nt * 8) * 80);
            mma16(s[0][nt], qa[0][0], kb[0], kb[1]);
            mma16(s[0][nt], qa[1][0], kb[2], kb[3]);
            mma16(s[1][nt], qa[0][1], kb[0], kb[1]);
            mma16(s[1][nt], qa[1][1], kb[2], kb[3]);
        }

        unsigned pa[2][2][4];
#pragma unroll
        for (int ks = 0; ks < 2; ks++)
#pragma unroll
            for (int mt = 0; mt < 2; mt++) {
                pa[ks][mt][0] = ex2h2(pack2(s[mt][2 * ks][0],     s[mt][2 * ks][1]));
                pa[ks][mt][1] = ex2h2(pack2(s[mt][2 * ks][2],     s[mt][2 * ks][3]));
                pa[ks][mt][2] = ex2h2(pack2(s[mt][2 * ks + 1][0], s[mt][2 * ks + 1][1]));
                pa[ks][mt][3] = ex2h2(pack2(s[mt][2 * ks + 1][2], s[mt][2 * ks + 1][3]));
            }

#pragma unroll
        for (int ks = 0; ks < 2; ks++) {
            const uint32_t off = (uint32_t)(jc * 32 + ks * 16) * 80;
            unsigned v01[4], v23[4], v4[2];
            ldsm4t(v01[0], v01[1], v01[2], v01[3], vb4 + off);
            ldsm4t(v23[0], v23[1], v23[2], v23[3], vb4 + off + 32);
            ldsm2t(v4[0], v4[1], vb2 + off);
#pragma unroll
            for (int mt = 0; mt < 2; mt++) {
                mma16(o[mt][0], pa[ks][mt], v01[0], v01[1]);
                mma16(o[mt][1], pa[ks][mt], v01[2], v01[3]);
                mma16(o[mt][2], pa[ks][mt], v23[0], v23[1]);
                mma16(o[mt][3], pa[ks][mt], v23[2], v23[3]);
                mma16(o4[mt],   pa[ks][mt], v4[0],  v4[1]);
            }
        }
    }

#pragma unroll
    for (int mt = 0; mt < 2; mt++) {
#pragma unroll
        for (int hi = 0; hi < 2; hi++) {
            const float sum = __shfl_sync(0xffffffffu, o4[mt][2 * hi], lane & ~3);
            const float inv = __fdividef(1.0f, sum);
            const int l = warp * 32 + mt * 16 + hi * 8 + g;
#pragma unroll
            for (int dt = 0; dt < 4; dt++) {
                const int c = ah * HD + dt * 8 + 2 * tg;
                *(unsigned*)(O + ((long)(b * LSEQ + l)) * CDIM + c) =
                    pack2(o[mt][dt][2 * hi] * inv, o[mt][dt][2 * hi + 1] * inv);
            }
        }
    }
}

// ============================================================================
// launch
// ============================================================================
extern "C" void kernel_launch(void* const* d_in, const int* in_sizes, int n_in,
                              void* d_out, int out_size)
{
    const float* x  = (const float*)d_in[0];
    const float* Wq = (const float*)d_in[1];
    const float* bq = (const float*)d_in[2];
    const float* Wk = (const float*)d_in[3];
    const float* bk = (const float*)d_in[4];
    const float* Wv = (const float*)d_in[5];
    const float* bv = (const float*)d_in[6];
    const float* Wp = (const float*)d_in[7];
    const float* bp = (const float*)d_in[8];

    __half *xh, *qp, *kp, *vp, *op, *wt;
    cudaGetSymbolAddress((void**)&xh, g_X);
    cudaGetSymbolAddress((void**)&qp, g_Q);
    cudaGetSymbolAddress((void**)&kp, g_K);
    cudaGetSymbolAddress((void**)&vp, g_V);
    cudaGetSymbolAddress((void**)&op, g_O);
    cudaGetSymbolAddress((void**)&wt, g_Wt);

    cudaFuncSetAttribute(gemm3_kernel<0>,
                         cudaFuncAttributeMaxDynamicSharedMemorySize, GEMM_SMEM_BYTES);
    cudaFuncSetAttribute(gemm3_kernel<1>,
                         cudaFuncAttributeMaxDynamicSharedMemorySize, GEMM_SMEM_BYTES);

    prep_kernel<<<16384 + 64, 256>>>(x, xh, Wq, Wk, Wv, Wp, wt);

    // persistent QKV: 6 weight/n slices x 49 y-slots = 294 CTAs (one wave)
    dim3 gqkv(6, 49);
    gemm3_kernel<0><<<gqkv, 256, GEMM_SMEM_BYTES>>>(
        xh, wt, bq, bk, bv, qp, kp, vp);

    attn_f16_kernel<<<NBATCH * HEADS, 256>>>(qp, kp, vp, op);

    // persistent proj: 2 n-slices x 148 y-slots = 296 CTAs (one wave)
    dim3 gp(2, 148);
    gemm3_kernel<1><<<gp, 256, GEMM_SMEM_BYTES>>>(
        op, wt + 3 * CDIM * CDIM, bp, bp, bp, d_out, d_out, d_out);
}